// round 4
// baseline (speedup 1.0000x reference)
#include <cuda_runtime.h>
#include <math.h>

#define BB 16
#define CC 64
#define HH 144
#define WW 144
#define hs 48
#define wsz 48
#define G9 9
#define C9 576
#define HW (hs*wsz)          // 2304
#define NPIX 36864.0f        // B*h*w
#define EPSV 1e-5f

// ---- static scratch (no allocations allowed) ----
__device__ float g_focus[BB*C9*HW];   // 85 MB
__device__ float g_mixed[BB*C9*HW];   // 85 MB
__device__ float g_s[BB*CC*HW];       // 9.4 MB
__device__ float g_sum1[C9], g_sq1[C9], g_scale1[C9], g_shift1[C9];
__device__ float g_sum2[CC], g_sq2[CC], g_scale2[CC], g_shift2[CC];

// ---------------------------------------------------------------
// K1: maxpool3x3(stride1,pad1) + focus_downsample (fused).
// One thread per (b,c,hh,ww) computes all 9 group outputs from a 5x5 window.
// Also zeroes bn1 accumulators (block 0).
// ---------------------------------------------------------------
__global__ void k_pool_focus(const float* __restrict__ x) {
    if (blockIdx.x == 0) {
        for (int i = threadIdx.x; i < C9; i += 256) { g_sum1[i] = 0.f; g_sq1[i] = 0.f; }
    }
    int idx = blockIdx.x * 256 + threadIdx.x;
    if (idx >= BB*CC*HW) return;
    int ww = idx % wsz; int t = idx / wsz;
    int hh = t % hs;    t /= hs;
    int c  = t % CC;    int b = t / CC;

    const float* xp = x + (size_t)(b*CC + c) * HH * WW;
    int r0 = hh*3 - 1, c0 = ww*3 - 1;
    float v[5][5];
#pragma unroll
    for (int r = 0; r < 5; r++) {
        int rr = r0 + r; bool rok = (rr >= 0 && rr < HH);
#pragma unroll
        for (int q = 0; q < 5; q++) {
            int cc = c0 + q;
            v[r][q] = (rok && cc >= 0 && cc < WW) ? xp[rr*WW + cc] : -INFINITY;
        }
    }
    float hm[5][3];
#pragma unroll
    for (int r = 0; r < 5; r++)
#pragma unroll
        for (int j = 0; j < 3; j++)
            hm[r][j] = fmaxf(fmaxf(v[r][j], v[r][j+1]), v[r][j+2]);

#pragma unroll
    for (int i = 0; i < 3; i++)
#pragma unroll
        for (int j = 0; j < 3; j++) {
            float m = fmaxf(fmaxf(hm[i][j], hm[i+1][j]), hm[i+2][j]);
            g_focus[((size_t)b*C9 + (i*3+j)*CC + c) * HW + hh*wsz + ww] = m;
        }
}

// ---------------------------------------------------------------
// K2: mixer GEMM.  Per (b,g): out[o,p] = sum_i W[g,o,i] * in[i,p]
// Block: 64 o x 256 p, thread micro-tile 8x8.  K=64 in 4 chunks of 16.
// Epilogue: per-channel sum / sumsq partials -> atomicAdd (bn1 stats).
// ---------------------------------------------------------------
__global__ void k_mixer(const float* __restrict__ wmix) {
    __shared__ __align__(16) float Ws[64*64];
    __shared__ __align__(16) float Xs[16*256];
    int tid = threadIdx.x;
    int pt = blockIdx.x;            // 0..8 pixel tile
    int g  = blockIdx.y;            // 0..8 group
    int b  = blockIdx.z;            // 0..15

    const float* wg = wmix + g*4096;
#pragma unroll
    for (int k = 0; k < 16; k++) Ws[tid + k*256] = wg[tid + k*256];

    size_t base = ((size_t)b*C9 + g*CC) * HW + pt*256;
    int tp = tid & 31, to = tid >> 5;      // tp: p/8 lane, to: o/8 warp

    float acc[8][8];
#pragma unroll
    for (int a = 0; a < 8; a++)
#pragma unroll
        for (int p = 0; p < 8; p++) acc[a][p] = 0.f;

    for (int kc = 0; kc < 4; kc++) {
        __syncthreads();
#pragma unroll
        for (int k = 0; k < 16; k++) {
            int e = tid + k*256; int i = e >> 8; int p = e & 255;
            Xs[e] = g_focus[base + (size_t)(kc*16 + i)*HW + p];
        }
        __syncthreads();
#pragma unroll
        for (int i = 0; i < 16; i++) {
            int ig = kc*16 + i;
            float a[8];
#pragma unroll
            for (int oo = 0; oo < 8; oo++) a[oo] = Ws[(to*8+oo)*64 + ig];
            float4 b0 = *(const float4*)&Xs[i*256 + tp*8];
            float4 b1 = *(const float4*)&Xs[i*256 + tp*8 + 4];
            float bb[8] = {b0.x,b0.y,b0.z,b0.w,b1.x,b1.y,b1.z,b1.w};
#pragma unroll
            for (int oo = 0; oo < 8; oo++)
#pragma unroll
                for (int pp = 0; pp < 8; pp++)
                    acc[oo][pp] += a[oo] * bb[pp];
        }
    }
    // store
    float* outp = g_mixed + base;
#pragma unroll
    for (int oo = 0; oo < 8; oo++) {
        int o = to*8 + oo;
        float4 r0 = make_float4(acc[oo][0],acc[oo][1],acc[oo][2],acc[oo][3]);
        float4 r1 = make_float4(acc[oo][4],acc[oo][5],acc[oo][6],acc[oo][7]);
        *(float4*)&outp[(size_t)o*HW + tp*8]     = r0;
        *(float4*)&outp[(size_t)o*HW + tp*8 + 4] = r1;
    }
    // bn1 partials: warp owns 8 channels (o rows), reduce over 32 p-lanes
#pragma unroll
    for (int oo = 0; oo < 8; oo++) {
        float s = 0.f, q = 0.f;
#pragma unroll
        for (int pp = 0; pp < 8; pp++) { float v = acc[oo][pp]; s += v; q += v*v; }
#pragma unroll
        for (int off = 16; off > 0; off >>= 1) {
            s += __shfl_xor_sync(0xffffffffu, s, off);
            q += __shfl_xor_sync(0xffffffffu, q, off);
        }
        if (tp == 0) {
            int ch = g*CC + to*8 + oo;
            atomicAdd(&g_sum1[ch], s);
            atomicAdd(&g_sq1[ch], q);
        }
    }
}

// ---------------------------------------------------------------
// K3: finalize bn1 scale/shift; zero bn2 accumulators.
// ---------------------------------------------------------------
__global__ void k_fin1(const float* __restrict__ gm, const float* __restrict__ bm) {
    int i = threadIdx.x;
    if (i < C9) {
        float mean = g_sum1[i] / NPIX;
        float var  = g_sq1[i] / NPIX - mean*mean;
        float sc = gm[i] * rsqrtf(var + EPSV);
        g_scale1[i] = sc;
        g_shift1[i] = bm[i] - mean*sc;
    }
    if (i < CC) { g_sum2[i] = 0.f; g_sq2[i] = 0.f; }
}

// ---------------------------------------------------------------
// K4: fused 4-way dwconv on x_tem (bn1 applied on load).
// Shear transforms collapsed to diagonal stencils:
//   h1: x[i+u-5, j+v-1]            (w_h1[u,v], 11x3)
//   v1: x[i+u-1, j+v-5]            (w_v1[u,v], 3x11)
//   h2: x[i+u-5, j+(v-1)-(u-5)]    (w_h2[u,v], 11x3)
//   w2: x[i+(u-1)-(v-5), j+v-5]    (w_v2[u,v], 3x11)
// One block per (b,c): 60x60 smem tile (halo 6), thread = 3x3 outputs.
// Epilogue: bn2 sum/sumsq partials.
// ---------------------------------------------------------------
__global__ void k_conv(const float* __restrict__ wh1, const float* __restrict__ wv1,
                       const float* __restrict__ wh2, const float* __restrict__ wv2) {
    __shared__ float T[60*60];
    __shared__ float swh1[33], swv1[33], swh2[33], swv2[33];
    __shared__ float rs[8], rq[8];
    int tid = threadIdx.x;
    int bc = blockIdx.x; int c = bc & 63; int b = bc >> 6;

    float sc = g_scale1[c], sh = g_shift1[c];
    const float* inp = g_mixed + ((size_t)b*C9 + c) * HW;
    for (int e = tid; e < 3600; e += 256) {
        int tr = e / 60, tc = e % 60;
        int r = tr - 6, q = tc - 6;
        T[e] = (r >= 0 && r < hs && q >= 0 && q < wsz) ? fmaf(inp[r*wsz + q], sc, sh) : 0.f;
    }
    if (tid < 33) {
        swh1[tid] = wh1[c*33 + tid]; swv1[tid] = wv1[c*33 + tid];
        swh2[tid] = wh2[c*33 + tid]; swv2[tid] = wv2[c*33 + tid];
    }
    __syncthreads();

    int tx = tid & 15, ty = tid >> 4;
    int i0 = ty*3, j0 = tx*3;
    float acc[3][3] = {{0.f,0.f,0.f},{0.f,0.f,0.f},{0.f,0.f,0.f}};
#define TT(r,q) T[((r)+6)*60 + ((q)+6)]

    // ---- h1: vertical 11-tap, 3 cols ----
#pragma unroll
    for (int v = 0; v < 3; v++) {
        float wr[11];
#pragma unroll
        for (int u = 0; u < 11; u++) wr[u] = swh1[u*3 + v];
        int dc = v - 1;
#pragma unroll
        for (int ox = 0; ox < 3; ox++) {
            float col[13];
#pragma unroll
            for (int r = 0; r < 13; r++) col[r] = TT(i0 + r - 5, j0 + ox + dc);
#pragma unroll
            for (int oy = 0; oy < 3; oy++)
#pragma unroll
                for (int u = 0; u < 11; u++) acc[oy][ox] += wr[u] * col[oy + u];
        }
    }
    // ---- v1: horizontal 11-tap, 3 rows ----
#pragma unroll
    for (int u = 0; u < 3; u++) {
        float wr[11];
#pragma unroll
        for (int v = 0; v < 11; v++) wr[v] = swv1[u*11 + v];
        int dr = u - 1;
#pragma unroll
        for (int oy = 0; oy < 3; oy++) {
            float row[13];
#pragma unroll
            for (int q = 0; q < 13; q++) row[q] = TT(i0 + oy + dr, j0 + q - 5);
#pragma unroll
            for (int ox = 0; ox < 3; ox++)
#pragma unroll
                for (int v = 0; v < 11; v++) acc[oy][ox] += wr[v] * row[ox + v];
        }
    }
    // ---- h2: anti-diagonal (dr=u-5, dc=(v-1)-(u-5)) ----
#pragma unroll
    for (int v = 0; v < 3; v++) {
        float wr[11];
#pragma unroll
        for (int u = 0; u < 11; u++) wr[u] = swh2[u*3 + v];
        int e = v - 1;
#pragma unroll
        for (int oy = 0; oy < 3; oy++)
#pragma unroll
            for (int ox = 0; ox < 3; ox++)
#pragma unroll
                for (int u = 0; u < 11; u++)
                    acc[oy][ox] += wr[u] * TT(i0 + oy + u - 5, j0 + ox + e - (u - 5));
    }
    // ---- w2: anti-diagonal (dr=(u-1)-(v-5), dc=v-5) ----
#pragma unroll
    for (int u = 0; u < 3; u++) {
        float wr[11];
#pragma unroll
        for (int v = 0; v < 11; v++) wr[v] = swv2[u*11 + v];
        int e2 = u - 1;
#pragma unroll
        for (int oy = 0; oy < 3; oy++)
#pragma unroll
            for (int ox = 0; ox < 3; ox++)
#pragma unroll
                for (int v = 0; v < 11; v++)
                    acc[oy][ox] += wr[v] * TT(i0 + oy + e2 - (v - 5), j0 + ox + v - 5);
    }
#undef TT

    float ls = 0.f, lq = 0.f;
    float* sp = g_s + ((size_t)b*CC + c) * HW;
#pragma unroll
    for (int oy = 0; oy < 3; oy++)
#pragma unroll
        for (int ox = 0; ox < 3; ox++) {
            float val = acc[oy][ox];
            sp[(i0 + oy)*wsz + j0 + ox] = val;
            ls += val; lq += val*val;
        }
#pragma unroll
    for (int off = 16; off > 0; off >>= 1) {
        ls += __shfl_xor_sync(0xffffffffu, ls, off);
        lq += __shfl_xor_sync(0xffffffffu, lq, off);
    }
    int lane = tid & 31, wid = tid >> 5;
    if (lane == 0) { rs[wid] = ls; rq[wid] = lq; }
    __syncthreads();
    if (tid == 0) {
        float s = 0.f, q = 0.f;
#pragma unroll
        for (int w = 0; w < 8; w++) { s += rs[w]; q += rq[w]; }
        atomicAdd(&g_sum2[c], s);
        atomicAdd(&g_sq2[c], q);
    }
}

// ---------------------------------------------------------------
// K5: finalize bn2 scale/shift.
// ---------------------------------------------------------------
__global__ void k_fin2(const float* __restrict__ gn, const float* __restrict__ bn) {
    int i = threadIdx.x;
    if (i < CC) {
        float mean = g_sum2[i] / NPIX;
        float var  = g_sq2[i] / NPIX - mean*mean;
        float sc = gn[i] * rsqrtf(var + EPSV);
        g_scale2[i] = sc;
        g_shift2[i] = bn[i] - mean*sc;
    }
}

// ---------------------------------------------------------------
// K6: concat + pixel_shuffle3 + sigmoid gate (fused).
// Thread = one (b,c,hh,ww) low-res pixel -> 9 hi-res outputs.
// att channel k = c*9 + r*3 + s; k<64 -> bn2(s buf), else -> bn1(mixed).
// ---------------------------------------------------------------
__global__ void k_final(const float* __restrict__ x, float* __restrict__ out) {
    int ww = threadIdx.x;                        // 0..47
    int hh = blockIdx.x * blockDim.y + threadIdx.y;
    int c = blockIdx.y, b = blockIdx.z;
    size_t pix = (size_t)hh*wsz + ww;

    float att[9];
#pragma unroll
    for (int t = 0; t < 9; t++) {
        int k = c*9 + t;
        float v;
        if (k < CC)
            v = fmaf(g_s[((size_t)b*CC + k)*HW + pix], g_scale2[k], g_shift2[k]);
        else
            v = fmaf(g_mixed[((size_t)b*C9 + k)*HW + pix], g_scale1[k], g_shift1[k]);
        att[t] = v;
    }
    const float* xp = x + (size_t)(b*CC + c) * HH * WW;
    float* op = out + (size_t)(b*CC + c) * HH * WW;
#pragma unroll
    for (int r = 0; r < 3; r++)
#pragma unroll
        for (int s2 = 0; s2 < 3; s2++) {
            int y = hh*3 + r, xx = ww*3 + s2;
            float a = att[r*3 + s2];
            float sig = 1.f / (1.f + expf(-a));
            op[y*WW + xx] = xp[y*WW + xx] * sig;
        }
}

// ---------------------------------------------------------------
extern "C" void kernel_launch(void* const* d_in, const int* in_sizes, int n_in,
                              void* d_out, int out_size) {
    const float* x       = (const float*)d_in[0];
    const float* w_mixer = (const float*)d_in[1];
    const float* g_mnorm = (const float*)d_in[2];
    const float* b_mnorm = (const float*)d_in[3];
    const float* w_h1    = (const float*)d_in[4];
    const float* w_v1    = (const float*)d_in[5];
    const float* w_h2    = (const float*)d_in[6];
    const float* w_v2    = (const float*)d_in[7];
    const float* g_norm  = (const float*)d_in[8];
    const float* b_norm  = (const float*)d_in[9];

    k_pool_focus<<<(BB*CC*HW + 255)/256, 256>>>(x);
    k_mixer<<<dim3(9, 9, 16), 256>>>(w_mixer);
    k_fin1<<<1, 576>>>(g_mnorm, b_mnorm);
    k_conv<<<BB*CC, 256>>>(w_h1, w_v1, w_h2, w_v2);
    k_fin2<<<1, 64>>>(g_norm, b_norm);
    k_final<<<dim3(12, 64, 16), dim3(48, 4)>>>(x, (float*)d_out);
}

// round 5
// speedup vs baseline: 1.1178x; 1.1178x over previous
#include <cuda_runtime.h>
#include <math.h>

#define BB 16
#define CC 64
#define HH 144
#define WW 144
#define hs 48
#define wsz 48
#define G9 9
#define C9 576
#define HW (hs*wsz)          // 2304
#define NPIX 36864.0f        // B*h*w
#define EPSV 1e-5f

typedef unsigned long long ull;

// ---- packed f32x2 helpers (sm_103a FFMA2 path) ----
__device__ __forceinline__ ull ffma2(ull a, ull b, ull c) {
    ull d; asm("fma.rn.f32x2 %0, %1, %2, %3;" : "=l"(d) : "l"(a), "l"(b), "l"(c)); return d;
}
__device__ __forceinline__ ull add2(ull a, ull b) {
    ull d; asm("add.rn.f32x2 %0, %1, %2;" : "=l"(d) : "l"(a), "l"(b)); return d;
}
__device__ __forceinline__ ull pack2(float lo, float hi) {
    ull d; asm("mov.b64 %0, {%1, %2};" : "=l"(d) : "f"(lo), "f"(hi)); return d;
}
__device__ __forceinline__ void unpack2(ull v, float& lo, float& hi) {
    asm("mov.b64 {%0, %1}, %2;" : "=f"(lo), "=f"(hi) : "l"(v));
}

// ---- static scratch ----
__device__ float g_focus[BB*C9*HW];   // 85 MB
__device__ float g_mixed[BB*C9*HW];   // 85 MB
__device__ float g_s[BB*CC*HW];       // 9.4 MB
__device__ float g_sum1[C9], g_sq1[C9];
__device__ float g_sum2[CC], g_sq2[CC];

// ---------------------------------------------------------------
// K1: maxpool3x3 + focus_downsample fused; zero bn accumulators.
// ---------------------------------------------------------------
__global__ void k_pool_focus(const float* __restrict__ x) {
    if (blockIdx.x == 0) {
        for (int i = threadIdx.x; i < C9; i += 256) { g_sum1[i] = 0.f; g_sq1[i] = 0.f; }
        if (threadIdx.x < CC) { g_sum2[threadIdx.x] = 0.f; g_sq2[threadIdx.x] = 0.f; }
    }
    int idx = blockIdx.x * 256 + threadIdx.x;
    if (idx >= BB*CC*HW) return;
    int ww = idx % wsz; int t = idx / wsz;
    int hh = t % hs;    t /= hs;
    int c  = t % CC;    int b = t / CC;

    const float* xp = x + (size_t)(b*CC + c) * HH * WW;
    int r0 = hh*3 - 1, c0 = ww*3 - 1;
    float v[5][5];
#pragma unroll
    for (int r = 0; r < 5; r++) {
        int rr = r0 + r; bool rok = (rr >= 0 && rr < HH);
#pragma unroll
        for (int q = 0; q < 5; q++) {
            int cc = c0 + q;
            v[r][q] = (rok && cc >= 0 && cc < WW) ? xp[rr*WW + cc] : -INFINITY;
        }
    }
    float hm[5][3];
#pragma unroll
    for (int r = 0; r < 5; r++)
#pragma unroll
        for (int j = 0; j < 3; j++)
            hm[r][j] = fmaxf(fmaxf(v[r][j], v[r][j+1]), v[r][j+2]);
#pragma unroll
    for (int i = 0; i < 3; i++)
#pragma unroll
        for (int j = 0; j < 3; j++) {
            float m = fmaxf(fmaxf(hm[i][j], hm[i+1][j]), hm[i+2][j]);
            g_focus[((size_t)b*C9 + (i*3+j)*CC + c) * HW + hh*wsz + ww] = m;
        }
}

// ---------------------------------------------------------------
// K2: mixer GEMM with packed f32x2 FMA.
// Block: 64 o x 256 p; thread 8o x 8p (4 pixel-pairs packed).
// ---------------------------------------------------------------
__global__ void k_mixer(const float* __restrict__ wmix) {
    __shared__ __align__(16) float Ws[64*64];
    __shared__ __align__(16) float Xs[16*256];
    int tid = threadIdx.x;
    int pt = blockIdx.x, g = blockIdx.y, b = blockIdx.z;

    const float* wg = wmix + g*4096;
#pragma unroll
    for (int k = 0; k < 16; k++) Ws[tid + k*256] = wg[tid + k*256];

    size_t base = ((size_t)b*C9 + g*CC) * HW + pt*256;
    int tp = tid & 31, to = tid >> 5;

    ull acc2[8][4];
#pragma unroll
    for (int oo = 0; oo < 8; oo++)
#pragma unroll
        for (int j = 0; j < 4; j++) acc2[oo][j] = 0ull;

    for (int kc = 0; kc < 4; kc++) {
        __syncthreads();
#pragma unroll
        for (int k = 0; k < 16; k++) {
            int e = tid + k*256; int i = e >> 8; int p = e & 255;
            Xs[e] = g_focus[base + (size_t)(kc*16 + i)*HW + p];
        }
        __syncthreads();
#pragma unroll
        for (int i = 0; i < 16; i++) {
            int ig = kc*16 + i;
            ull b2[4];
            const ull* xr = (const ull*)&Xs[i*256 + tp*8];
            b2[0] = xr[0]; b2[1] = xr[1]; b2[2] = xr[2]; b2[3] = xr[3];
#pragma unroll
            for (int oo = 0; oo < 8; oo++) {
                float a = Ws[(to*8+oo)*64 + ig];
                ull a2 = pack2(a, a);
#pragma unroll
                for (int j = 0; j < 4; j++)
                    acc2[oo][j] = ffma2(a2, b2[j], acc2[oo][j]);
            }
        }
    }
    float* outp = g_mixed + base;
#pragma unroll
    for (int oo = 0; oo < 8; oo++) {
        int o = to*8 + oo;
        float v[8];
#pragma unroll
        for (int j = 0; j < 4; j++) unpack2(acc2[oo][j], v[2*j], v[2*j+1]);
        *(float4*)&outp[(size_t)o*HW + tp*8]     = make_float4(v[0],v[1],v[2],v[3]);
        *(float4*)&outp[(size_t)o*HW + tp*8 + 4] = make_float4(v[4],v[5],v[6],v[7]);
        // bn1 partials
        ull S = add2(add2(acc2[oo][0], acc2[oo][1]), add2(acc2[oo][2], acc2[oo][3]));
        ull Q = 0ull;
#pragma unroll
        for (int j = 0; j < 4; j++) Q = ffma2(acc2[oo][j], acc2[oo][j], Q);
        float sl, sh2, ql, qh; unpack2(S, sl, sh2); unpack2(Q, ql, qh);
        float s = sl + sh2, q = ql + qh;
#pragma unroll
        for (int off = 16; off > 0; off >>= 1) {
            s += __shfl_xor_sync(0xffffffffu, s, off);
            q += __shfl_xor_sync(0xffffffffu, q, off);
        }
        if (tp == 0) {
            int ch = g*CC + to*8 + oo;
            atomicAdd(&g_sum1[ch], s);
            atomicAdd(&g_sq1[ch], q);
        }
    }
}

// ---------------------------------------------------------------
// K3: fused 4-way dwconv, TWO channels per block packed as f32x2.
// Tile: rows [-6,53] (60), cols [-9,58] (68) of float2.
// h1/v1: column/row strips. h2/w2: shared anti-diagonal strips
// (both collapse to row+col = const walks).
// bn1 scale/shift computed inline; bn2 partials in epilogue.
// ---------------------------------------------------------------
#define TSTR 68
__global__ __launch_bounds__(256, 2)
void k_conv(const float* __restrict__ wh1, const float* __restrict__ wv1,
            const float* __restrict__ wh2, const float* __restrict__ wv2,
            const float* __restrict__ gm,  const float* __restrict__ bm) {
    __shared__ float2 T2[60*TSTR];
    __shared__ float2 sw1[33], sv1[33], sw2[33], sv2[33];
    __shared__ float rs0[8], rq0[8], rs1[8], rq1[8];
    int tid = threadIdx.x;
    int bc = blockIdx.x; int cp = bc & 31; int b = bc >> 5;
    int c0 = cp*2, c1 = c0 + 1;

    float mn0 = g_sum1[c0] / NPIX, mn1 = g_sum1[c1] / NPIX;
    float vr0 = g_sq1[c0] / NPIX - mn0*mn0, vr1 = g_sq1[c1] / NPIX - mn1*mn1;
    float sc0 = gm[c0] * rsqrtf(vr0 + EPSV), sc1 = gm[c1] * rsqrtf(vr1 + EPSV);
    float sh0 = bm[c0] - mn0*sc0,            sh1 = bm[c1] - mn1*sc1;

    const float* p0 = g_mixed + ((size_t)b*C9 + c0) * HW;
    const float* p1 = p0 + HW;
    for (int e = tid; e < 60*TSTR; e += 256) {
        int tr = e / TSTR, tc = e % TSTR;
        int r = tr - 6, q = tc - 9;
        float2 v = make_float2(0.f, 0.f);
        if (r >= 0 && r < hs && q >= 0 && q < wsz) {
            v.x = fmaf(p0[r*wsz + q], sc0, sh0);
            v.y = fmaf(p1[r*wsz + q], sc1, sh1);
        }
        T2[e] = v;
    }
    if (tid < 132) {
        int a = tid / 33, j = tid % 33;
        const float* src = (a == 0) ? wh1 : (a == 1) ? wv1 : (a == 2) ? wh2 : wv2;
        float2 w = make_float2(src[c0*33 + j], src[c1*33 + j]);
        if (a == 0) sw1[j] = w; else if (a == 1) sv1[j] = w;
        else if (a == 2) sw2[j] = w; else sv2[j] = w;
    }
    __syncthreads();

    int tx = tid & 15, ty = tid >> 4;
    int i0 = ty*3, j0 = tx*3;
    ull acc[3][3];
#pragma unroll
    for (int a = 0; a < 3; a++)
#pragma unroll
        for (int bq = 0; bq < 3; bq++) acc[a][bq] = 0ull;

#define T2AT(r,q) (*(const ull*)&T2[((r)+6)*TSTR + ((q)+9)])

    // ---- h1: vertical 11-tap, 3 weight columns ----
#pragma unroll
    for (int v = 0; v < 3; v++) {
        ull wr[11];
#pragma unroll
        for (int u = 0; u < 11; u++) wr[u] = *(const ull*)&sw1[u*3 + v];
        int dc = v - 1;
#pragma unroll
        for (int ox = 0; ox < 3; ox++) {
            ull col[13];
#pragma unroll
            for (int t = 0; t < 13; t++) col[t] = T2AT(i0 + t - 5, j0 + ox + dc);
#pragma unroll
            for (int oy = 0; oy < 3; oy++)
#pragma unroll
                for (int u = 0; u < 11; u++)
                    acc[oy][ox] = ffma2(wr[u], col[oy + u], acc[oy][ox]);
        }
    }
    // ---- v1: horizontal 11-tap, 3 weight rows ----
#pragma unroll
    for (int u = 0; u < 3; u++) {
        ull wr[11];
#pragma unroll
        for (int v = 0; v < 11; v++) wr[v] = *(const ull*)&sv1[u*11 + v];
        int dr = u - 1;
#pragma unroll
        for (int oy = 0; oy < 3; oy++) {
            ull row[13];
#pragma unroll
            for (int t = 0; t < 13; t++) row[t] = T2AT(i0 + oy + dr, j0 + t - 5);
#pragma unroll
            for (int ox = 0; ox < 3; ox++)
#pragma unroll
                for (int v = 0; v < 11; v++)
                    acc[oy][ox] = ffma2(wr[v], row[ox + v], acc[oy][ox]);
        }
    }
    // ---- h2 + w2: shared anti-diagonal strips ----
    // h2 tap: acc[oy][ox] += wh2[u, e+1] * S_d[oy+u+1],   d = oy+ox+e
    // w2 tap: acc[oy][ox] += wv2[e+1, v] * S_d[oy+e-v+11], d = oy+ox+e
    // S_d[s] = value at (row = i0+s-6, col = j0+d+6-s)
#pragma unroll
    for (int ee = 0; ee < 3; ee++) {
        int e = ee - 1;
        ull wA[11], wB[11];
#pragma unroll
        for (int u = 0; u < 11; u++) wA[u] = *(const ull*)&sw2[u*3 + ee];
#pragma unroll
        for (int v = 0; v < 11; v++) wB[v] = *(const ull*)&sv2[ee*11 + v];
#pragma unroll
        for (int s2 = 0; s2 < 5; s2++) {        // s2 = oy+ox
            int d = s2 + e;                      // in [-1,5], always valid
            ull strip[15];
#pragma unroll
            for (int s = 0; s < 15; s++)
                strip[s] = T2AT(i0 + s - 6, j0 + d + 6 - s);
#pragma unroll
            for (int oy = 0; oy < 3; oy++) {
                int ox = s2 - oy;
                if (ox < 0 || ox > 2) continue;
#pragma unroll
                for (int u = 0; u < 11; u++)
                    acc[oy][ox] = ffma2(wA[u], strip[oy + u + 1], acc[oy][ox]);
#pragma unroll
                for (int v = 0; v < 11; v++)
                    acc[oy][ox] = ffma2(wB[v], strip[oy + e - v + 11], acc[oy][ox]);
            }
        }
    }
#undef T2AT

    // store + bn2 partials
    float* sp0 = g_s + ((size_t)b*CC + c0) * HW;
    float* sp1 = sp0 + HW;
    ull S = 0ull, Q = 0ull;
#pragma unroll
    for (int oy = 0; oy < 3; oy++)
#pragma unroll
        for (int ox = 0; ox < 3; ox++) {
            float v0, v1; unpack2(acc[oy][ox], v0, v1);
            sp0[(i0 + oy)*wsz + j0 + ox] = v0;
            sp1[(i0 + oy)*wsz + j0 + ox] = v1;
            S = add2(S, acc[oy][ox]);
            Q = ffma2(acc[oy][ox], acc[oy][ox], Q);
        }
    float s0, s1, q0, q1; unpack2(S, s0, s1); unpack2(Q, q0, q1);
#pragma unroll
    for (int off = 16; off > 0; off >>= 1) {
        s0 += __shfl_xor_sync(0xffffffffu, s0, off);
        q0 += __shfl_xor_sync(0xffffffffu, q0, off);
        s1 += __shfl_xor_sync(0xffffffffu, s1, off);
        q1 += __shfl_xor_sync(0xffffffffu, q1, off);
    }
    int lane = tid & 31, wid = tid >> 5;
    if (lane == 0) { rs0[wid] = s0; rq0[wid] = q0; rs1[wid] = s1; rq1[wid] = q1; }
    __syncthreads();
    if (tid == 0) {
        float a0 = 0.f, b0v = 0.f, a1 = 0.f, b1v = 0.f;
#pragma unroll
        for (int w = 0; w < 8; w++) { a0 += rs0[w]; b0v += rq0[w]; a1 += rs1[w]; b1v += rq1[w]; }
        atomicAdd(&g_sum2[c0], a0); atomicAdd(&g_sq2[c0], b0v);
        atomicAdd(&g_sum2[c1], a1); atomicAdd(&g_sq2[c1], b1v);
    }
}

// ---------------------------------------------------------------
// K4: concat + pixel_shuffle3 + sigmoid gate; BN finalize inline.
// ---------------------------------------------------------------
__global__ void k_final(const float* __restrict__ x, float* __restrict__ out,
                        const float* __restrict__ gm, const float* __restrict__ bm,
                        const float* __restrict__ gn, const float* __restrict__ bn) {
    __shared__ float ssc[9], ssh[9];
    int c = blockIdx.y, b = blockIdx.z;
    int tid = threadIdx.y * 48 + threadIdx.x;
    if (tid < 9) {
        int k = c*9 + tid;
        float mean, var, sc, sh;
        if (k < CC) {
            mean = g_sum2[k] / NPIX; var = g_sq2[k] / NPIX - mean*mean;
            sc = gn[k] * rsqrtf(var + EPSV); sh = bn[k] - mean*sc;
        } else {
            mean = g_sum1[k] / NPIX; var = g_sq1[k] / NPIX - mean*mean;
            sc = gm[k] * rsqrtf(var + EPSV); sh = bm[k] - mean*sc;
        }
        ssc[tid] = sc; ssh[tid] = sh;
    }
    __syncthreads();

    int ww = threadIdx.x;
    int hh = blockIdx.x * blockDim.y + threadIdx.y;
    size_t pix = (size_t)hh*wsz + ww;

    float att[9];
#pragma unroll
    for (int t = 0; t < 9; t++) {
        int k = c*9 + t;
        float v = (k < CC) ? g_s[((size_t)b*CC + k)*HW + pix]
                           : g_mixed[((size_t)b*C9 + k)*HW + pix];
        att[t] = fmaf(v, ssc[t], ssh[t]);
    }
    const float* xp = x + (size_t)(b*CC + c) * HH * WW;
    float* op = out + (size_t)(b*CC + c) * HH * WW;
#pragma unroll
    for (int r = 0; r < 3; r++)
#pragma unroll
        for (int s2 = 0; s2 < 3; s2++) {
            int y = hh*3 + r, xx = ww*3 + s2;
            float sig = 1.f / (1.f + __expf(-att[r*3 + s2]));
            op[y*WW + xx] = xp[y*WW + xx] * sig;
        }
}

// ---------------------------------------------------------------
extern "C" void kernel_launch(void* const* d_in, const int* in_sizes, int n_in,
                              void* d_out, int out_size) {
    const float* x       = (const float*)d_in[0];
    const float* w_mixer = (const float*)d_in[1];
    const float* g_mnorm = (const float*)d_in[2];
    const float* b_mnorm = (const float*)d_in[3];
    const float* w_h1    = (const float*)d_in[4];
    const float* w_v1    = (const float*)d_in[5];
    const float* w_h2    = (const float*)d_in[6];
    const float* w_v2    = (const float*)d_in[7];
    const float* g_norm  = (const float*)d_in[8];
    const float* b_norm  = (const float*)d_in[9];

    k_pool_focus<<<(BB*CC*HW + 255)/256, 256>>>(x);
    k_mixer<<<dim3(9, 9, 16), 256>>>(w_mixer);
    k_conv<<<BB*32, 256>>>(w_h1, w_v1, w_h2, w_v2, g_mnorm, b_mnorm);
    k_final<<<dim3(12, 64, 16), dim3(48, 4)>>>(x, (float*)d_out, g_mnorm, b_mnorm, g_norm, b_norm);
}